// round 1
// baseline (speedup 1.0000x reference)
#include <cuda_runtime.h>
#include <cuda_bf16.h>

#define TS   65536
#define MD   256
#define NE   8
#define NH   1024
#define CAPX 20480
#define NB1  256
#define PITCH 68

// ---------------- scratch (device globals; no allocations) ----------------
__device__ unsigned char g_e0[TS], g_e1[TS];
__device__ float g_g0[TS], g_g1[TS];
__device__ int   g_cnt[NB1][NE][2];
__device__ float g_gs[NB1][NE];
__device__ int   g_blkoff[NB1][NE][2];
__device__ int   g_cnt0[NE];
__device__ int   g_lim1[NE];
__device__ int   g_valid0[NE];
__device__ int   g_base[NE];
__device__ int   g_vcnt[NE];
__device__ int   g_atok[2 * TS];
__device__ float g_agate[2 * TS];

// ---------------- K1: gating (softmax + top2 + block stats) ----------------
__global__ __launch_bounds__(256) void k1_gate(const float* __restrict__ x,
                                               const float* __restrict__ wg) {
    __shared__ float wgs[NE][MD];
    __shared__ float s_gs[8][NE];
    __shared__ int   s_c0[8][NE], s_c1[8][NE];
    int tid = threadIdx.x, w = tid >> 5, lane = tid & 31;
    for (int i = tid; i < NE * MD; i += 256) wgs[i >> 8][i & 255] = wg[i];
    __syncthreads();

    float gsum[NE]; int c0[NE], c1[NE];
#pragma unroll
    for (int e = 0; e < NE; e++) { gsum[e] = 0.f; c0[e] = 0; c1[e] = 0; }

    int tok0 = blockIdx.x * 256 + w * 32;
    for (int it = 0; it < 32; it++) {
        int t = tok0 + it;
        const float* xr = x + (size_t)t * MD;
        float acc[NE];
#pragma unroll
        for (int e = 0; e < NE; e++) acc[e] = 0.f;
#pragma unroll
        for (int j = 0; j < 8; j++) {
            int c = lane + 32 * j;
            float xv = xr[c];
#pragma unroll
            for (int e = 0; e < NE; e++) acc[e] += xv * wgs[e][c];
        }
#pragma unroll
        for (int e = 0; e < NE; e++) {
            float v = acc[e];
            v += __shfl_down_sync(0xffffffffu, v, 16);
            v += __shfl_down_sync(0xffffffffu, v, 8);
            v += __shfl_down_sync(0xffffffffu, v, 4);
            v += __shfl_down_sync(0xffffffffu, v, 2);
            v += __shfl_down_sync(0xffffffffu, v, 1);
            acc[e] = v;
        }
        if (lane == 0) {
            float mx = acc[0];
#pragma unroll
            for (int e = 1; e < NE; e++) mx = fmaxf(mx, acc[e]);
            float g[NE]; float s = 0.f;
#pragma unroll
            for (int e = 0; e < NE; e++) { g[e] = expf(acc[e] - mx); s += g[e]; }
            float inv = 1.f / s;
            int b0 = 0; float v0 = -1.f;
#pragma unroll
            for (int e = 0; e < NE; e++) {
                g[e] *= inv; gsum[e] += g[e];
                if (g[e] > v0) { v0 = g[e]; b0 = e; }
            }
            int b1i = 0; float v1 = -2.f;
#pragma unroll
            for (int e = 0; e < NE; e++)
                if (e != b0 && g[e] > v1) { v1 = g[e]; b1i = e; }
            g_e0[t] = (unsigned char)b0; g_e1[t] = (unsigned char)b1i;
            g_g0[t] = v0; g_g1[t] = v1;
            c0[b0]++; c1[b1i]++;
        }
    }
    if (lane == 0) {
#pragma unroll
        for (int e = 0; e < NE; e++) { s_gs[w][e] = gsum[e]; s_c0[w][e] = c0[e]; s_c1[w][e] = c1[e]; }
    }
    __syncthreads();
    if (tid < NE) {
        float gs = 0.f; int a = 0, b = 0;
        for (int w2 = 0; w2 < 8; w2++) { gs += s_gs[w2][tid]; a += s_c0[w2][tid]; b += s_c1[w2][tid]; }
        g_gs[blockIdx.x][tid] = gs;
        g_cnt[blockIdx.x][tid][0] = a;
        g_cnt[blockIdx.x][tid][1] = b;
    }
}

// ---------------- K2: block scan + totals + loss ----------------
__global__ __launch_bounds__(256) void k2_scan(float* __restrict__ loss_out) {
    __shared__ int   s_cnt[NB1][16];
    __shared__ float s_g[NB1][NE];
    __shared__ int   s_tot[16];
    __shared__ float s_red[32][NE];
    int tid = threadIdx.x;
    for (int i = tid; i < NB1 * 16; i += 256) s_cnt[i >> 4][i & 15] = ((const int*)g_cnt)[i];
    for (int i = tid; i < NB1 * NE; i += 256) s_g[i >> 3][i & 7] = ((const float*)g_gs)[i];
    __syncthreads();
    if (tid < 16) {
        int run = 0;
        for (int b = 0; b < NB1; b++) { int v = s_cnt[b][tid]; s_cnt[b][tid] = run; run += v; }
        s_tot[tid] = run;
    }
    {
        int e = tid & 7, grp = tid >> 3;
        float p = 0.f;
        for (int b = grp * 8; b < grp * 8 + 8; b++) p += s_g[b][e];
        s_red[grp][e] = p;
    }
    __syncthreads();
    for (int i = tid; i < NB1 * 16; i += 256) ((int*)g_blkoff)[i] = s_cnt[i >> 4][i & 15];
    if (tid == 0) {
        int base = 0;
        for (int e = 0; e < NE; e++) {
            int c0t = s_tot[e * 2 + 0], c1t = s_tot[e * 2 + 1];
            g_cnt0[e] = c0t;
            int v0 = c0t < CAPX ? c0t : CAPX;
            int lim1 = CAPX - c0t; if (lim1 < 0) lim1 = 0;
            int v1 = c1t < lim1 ? c1t : lim1;
            g_valid0[e] = v0; g_lim1[e] = lim1;
            g_base[e] = base; g_vcnt[e] = v0 + v1;
            base += v0 + v1;
        }
        float loss = 0.f;
        for (int e = 0; e < NE; e++) {
            float gs = 0.f;
            for (int grp = 0; grp < 32; grp++) gs += s_red[grp][e];
            float me = gs / (float)TS;
            float ce = (float)s_tot[e * 2] / (float)TS;
            loss += me * ce;
        }
        *loss_out = loss * (float)NE;
    }
}

// ---------------- K3: deterministic ranks -> compacted assignment lists ----------------
__global__ __launch_bounds__(256) void k3_build() {
    __shared__ int wcnt[8][NE][2];
    __shared__ int wpre[8][NE][2];
    int tid = threadIdx.x, w = tid >> 5, lane = tid & 31;
    int t = blockIdx.x * 256 + tid;   // warp w covers consecutive tokens, lane ascending
    int e0 = g_e0[t], e1 = g_e1[t];
    float g0 = g_g0[t], g1 = g_g1[t];
    if (tid < 128) ((int*)wcnt)[tid] = 0;
    __syncthreads();
    unsigned m0 = __match_any_sync(0xffffffffu, e0);
    unsigned m1 = __match_any_sync(0xffffffffu, e1);
    unsigned lt = (1u << lane) - 1u;
    int r0 = __popc(m0 & lt);
    int r1 = __popc(m1 & lt);
    if ((m0 & lt) == 0) wcnt[w][e0][0] = __popc(m0);
    if ((m1 & lt) == 0) wcnt[w][e1][1] = __popc(m1);
    __syncthreads();
    if (tid < 16) {
        int e = tid >> 1, k = tid & 1;
        int run = 0;
        for (int w2 = 0; w2 < 8; w2++) { wpre[w2][e][k] = run; run += wcnt[w2][e][k]; }
    }
    __syncthreads();
    int b = blockIdx.x;
    int R0 = g_blkoff[b][e0][0] + wpre[w][e0][0] + r0;
    int R1 = g_blkoff[b][e1][1] + wpre[w][e1][1] + r1;
    if (R0 < CAPX) { int p = g_base[e0] + R0; g_atok[p] = t; g_agate[p] = g0; }
    if (R1 < g_lim1[e1]) { int p = g_base[e1] + g_valid0[e1] + R1; g_atok[p] = t; g_agate[p] = g1; }
}

// ---------------- K4: fused expert FFN (fp32 tiled GEMM x2) ----------------
__global__ __launch_bounds__(256, 2) void k4_ffn(
    const float* __restrict__ x,
    const float* __restrict__ w1, const float* __restrict__ b1,
    const float* __restrict__ w2, const float* __restrict__ b2,
    float* __restrict__ y) {
    int e = blockIdx.y;
    int cnt = g_vcnt[e];
    int row0 = blockIdx.x * 64;
    if (row0 >= cnt) return;
    int rows = min(64, cnt - row0);
    int base = g_base[e] + row0;

    extern __shared__ float sm[];
    float* XsT = sm;                      // [256][PITCH]
    float* HsT = XsT + 256 * PITCH;       // [64][PITCH]
    float* W1s = HsT + 64 * PITCH;        // [32][64]
    float* W2s = W1s + 32 * 64;           // [16][256]
    int*   toks = (int*)(W2s + 16 * 256); // [64]
    float* gts  = (float*)(toks + 64);    // [64]

    int tid = threadIdx.x;
    if (tid < 64) {
        if (tid < rows) { toks[tid] = g_atok[base + tid]; gts[tid] = g_agate[base + tid]; }
        else            { toks[tid] = 0; gts[tid] = 0.f; }
    }
    __syncthreads();
    {   // gather X tile transposed into smem
        int i = tid >> 2, part = tid & 3;
        const float4* xr = (const float4*)(x + (size_t)toks[i] * MD);
        bool live = i < rows;
#pragma unroll
        for (int j = 0; j < 16; j++) {
            int c4 = part * 16 + j;
            float4 v = live ? xr[c4] : make_float4(0.f, 0.f, 0.f, 0.f);
            int c = c4 * 4;
            XsT[(c + 0) * PITCH + i] = v.x;
            XsT[(c + 1) * PITCH + i] = v.y;
            XsT[(c + 2) * PITCH + i] = v.z;
            XsT[(c + 3) * PITCH + i] = v.w;
        }
    }
    int tg = tid >> 4;   // GEMM1: h-group   | GEMM2: token-group
    int mg = tid & 15;   // GEMM1: tok-group | GEMM2: m-group

    float acc[4][16];
#pragma unroll
    for (int b = 0; b < 4; b++)
#pragma unroll
        for (int j = 0; j < 16; j++) acc[b][j] = 0.f;

    for (int hc = 0; hc < 16; hc++) {
        float hacc[4][4];
#pragma unroll
        for (int a = 0; a < 4; a++)
#pragma unroll
            for (int b = 0; b < 4; b++) hacc[a][b] = 0.f;

        // ---- GEMM1: H_c(64x64) = X(64x256) @ W1[:, hc*64..] ----
        for (int ks = 0; ks < MD; ks += 32) {
            __syncthreads();
#pragma unroll
            for (int rep = 0; rep < 2; rep++) {
                int f = tid + rep * 256;             // [32][16] float4s
                int r = f >> 4, c4 = f & 15;
                float4 v = *(const float4*)(w1 + ((size_t)(e * MD + ks + r) * NH + hc * 64 + c4 * 4));
                *(float4*)&W1s[r * 64 + c4 * 4] = v;
            }
            __syncthreads();
#pragma unroll
            for (int s = 0; s < 32; s++) {
                float4 xv = *(const float4*)&XsT[(ks + s) * PITCH + mg * 4];
                float4 wv = *(const float4*)&W1s[s * 64 + tg * 4];
                hacc[0][0] += wv.x * xv.x; hacc[0][1] += wv.x * xv.y; hacc[0][2] += wv.x * xv.z; hacc[0][3] += wv.x * xv.w;
                hacc[1][0] += wv.y * xv.x; hacc[1][1] += wv.y * xv.y; hacc[1][2] += wv.y * xv.z; hacc[1][3] += wv.y * xv.w;
                hacc[2][0] += wv.z * xv.x; hacc[2][1] += wv.z * xv.y; hacc[2][2] += wv.z * xv.z; hacc[2][3] += wv.z * xv.w;
                hacc[3][0] += wv.w * xv.x; hacc[3][1] += wv.w * xv.y; hacc[3][2] += wv.w * xv.z; hacc[3][3] += wv.w * xv.w;
            }
        }
        {   // bias + relu, store H transposed
            const float* b1p = b1 + e * NH + hc * 64;
#pragma unroll
            for (int a = 0; a < 4; a++) {
                int h = tg * 4 + a;
                float bv = b1p[h];
                float4 o;
                o.x = fmaxf(hacc[a][0] + bv, 0.f);
                o.y = fmaxf(hacc[a][1] + bv, 0.f);
                o.z = fmaxf(hacc[a][2] + bv, 0.f);
                o.w = fmaxf(hacc[a][3] + bv, 0.f);
                *(float4*)&HsT[h * PITCH + mg * 4] = o;
            }
        }
        // ---- GEMM2: Out(64x256) += H_c(64x64) @ W2[hc*64.., :] ----
        for (int ks = 0; ks < 64; ks += 16) {
            __syncthreads();
#pragma unroll
            for (int q = 0; q < 4; q++) {
                int f = tid + q * 256;               // [16][64] float4s
                int r = f >> 6, c4 = f & 63;
                float4 v = *(const float4*)(w2 + ((size_t)(e * NH + hc * 64 + ks + r) * MD + c4 * 4));
                *(float4*)&W2s[r * 256 + c4 * 4] = v;
            }
            __syncthreads();
#pragma unroll
            for (int s = 0; s < 16; s++) {
                float4 hv = *(const float4*)&HsT[(ks + s) * PITCH + tg * 4];
                const float* wrow = &W2s[s * 256 + mg];   // stride-16 scalar: conflict-free
#pragma unroll
                for (int j = 0; j < 16; j++) {
                    float wvv = wrow[j * 16];
                    acc[0][j] += hv.x * wvv;
                    acc[1][j] += hv.y * wvv;
                    acc[2][j] += hv.z * wvv;
                    acc[3][j] += hv.w * wvv;
                }
            }
        }
    }
    // ---- epilogue: y[token] += gate * (out + b2) (<=2 adds per element: deterministic) ----
    const float* b2p = b2 + e * MD;
#pragma unroll
    for (int b = 0; b < 4; b++) {
        int t = tg * 4 + b;
        if (t < rows) {
            float g = gts[t];
            float* yr = y + (size_t)toks[t] * MD;
#pragma unroll
            for (int j = 0; j < 16; j++) {
                int m = mg + 16 * j;
                atomicAdd(&yr[m], g * (acc[b][j] + b2p[m]));
            }
        }
    }
}

// ---------------- launcher ----------------
extern "C" void kernel_launch(void* const* d_in, const int* in_sizes, int n_in,
                              void* d_out, int out_size) {
    const float* x  = (const float*)d_in[0];
    const float* wg = (const float*)d_in[1];
    const float* w1 = (const float*)d_in[2];
    const float* b1 = (const float*)d_in[3];
    const float* w2 = (const float*)d_in[4];
    const float* b2 = (const float*)d_in[5];
    float* y = (float*)d_out;
    float* loss = y + (size_t)TS * MD;

    cudaMemsetAsync(y, 0, (size_t)TS * MD * sizeof(float));
    k1_gate<<<NB1, 256>>>(x, wg);
    k2_scan<<<1, 256>>>(loss);
    k3_build<<<NB1, 256>>>();

    int smem = (256 * PITCH + 64 * PITCH + 32 * 64 + 16 * 256 + 128) * 4;  // 112128 B
    cudaFuncSetAttribute(k4_ffn, cudaFuncAttributeMaxDynamicSharedMemorySize, smem);
    k4_ffn<<<dim3((CAPX + 63) / 64, NE), 256, smem>>>(x, w1, b1, w2, b2, y);
}

// round 3
// speedup vs baseline: 1.0030x; 1.0030x over previous
#include <cuda_runtime.h>
#include <cuda_bf16.h>

#define TS   65536
#define MD   256
#define NE   8
#define NH   1024
#define CAPX 20480
#define NB1  256
#define PITCH 68

// ---------------- scratch (device globals; no allocations) ----------------
__device__ unsigned char g_e0[TS], g_e1[TS];
__device__ float g_g0[TS], g_g1[TS];
__device__ int   g_cnt[NB1][NE][2];
__device__ float g_gs[NB1][NE];
__device__ int   g_blkoff[NB1][NE][2];
__device__ int   g_cnt0[NE];
__device__ int   g_lim1[NE];
__device__ int   g_valid0[NE];
__device__ int   g_base[NE];
__device__ int   g_vcnt[NE];
__device__ int   g_atok[2 * TS];
__device__ float g_agate[2 * TS];

// ---------------- K1: gating (softmax + top2 + block stats) ----------------
__global__ __launch_bounds__(256) void k1_gate(const float* __restrict__ x,
                                               const float* __restrict__ wg) {
    __shared__ float wgs[NE][MD];
    __shared__ float s_gs[8][NE];
    __shared__ int   s_c0[8][NE], s_c1[8][NE];
    int tid = threadIdx.x, w = tid >> 5, lane = tid & 31;
    for (int i = tid; i < NE * MD; i += 256) wgs[i >> 8][i & 255] = wg[i];
    __syncthreads();

    float gsum[NE]; int c0[NE], c1[NE];
#pragma unroll
    for (int e = 0; e < NE; e++) { gsum[e] = 0.f; c0[e] = 0; c1[e] = 0; }

    int tok0 = blockIdx.x * 256 + w * 32;
    for (int it = 0; it < 32; it++) {
        int t = tok0 + it;
        const float* xr = x + (size_t)t * MD;
        float acc[NE];
#pragma unroll
        for (int e = 0; e < NE; e++) acc[e] = 0.f;
#pragma unroll
        for (int j = 0; j < 8; j++) {
            int c = lane + 32 * j;
            float xv = xr[c];
#pragma unroll
            for (int e = 0; e < NE; e++) acc[e] += xv * wgs[e][c];
        }
#pragma unroll
        for (int e = 0; e < NE; e++) {
            float v = acc[e];
            v += __shfl_down_sync(0xffffffffu, v, 16);
            v += __shfl_down_sync(0xffffffffu, v, 8);
            v += __shfl_down_sync(0xffffffffu, v, 4);
            v += __shfl_down_sync(0xffffffffu, v, 2);
            v += __shfl_down_sync(0xffffffffu, v, 1);
            acc[e] = v;
        }
        if (lane == 0) {
            float mx = acc[0];
#pragma unroll
            for (int e = 1; e < NE; e++) mx = fmaxf(mx, acc[e]);
            float g[NE]; float s = 0.f;
#pragma unroll
            for (int e = 0; e < NE; e++) { g[e] = expf(acc[e] - mx); s += g[e]; }
            float inv = 1.f / s;
            int b0 = 0; float v0 = -1.f;
#pragma unroll
            for (int e = 0; e < NE; e++) {
                g[e] *= inv; gsum[e] += g[e];
                if (g[e] > v0) { v0 = g[e]; b0 = e; }
            }
            int b1i = 0; float v1 = -2.f;
#pragma unroll
            for (int e = 0; e < NE; e++)
                if (e != b0 && g[e] > v1) { v1 = g[e]; b1i = e; }
            g_e0[t] = (unsigned char)b0; g_e1[t] = (unsigned char)b1i;
            g_g0[t] = v0; g_g1[t] = v1;
            c0[b0]++; c1[b1i]++;
        }
    }
    if (lane == 0) {
#pragma unroll
        for (int e = 0; e < NE; e++) { s_gs[w][e] = gsum[e]; s_c0[w][e] = c0[e]; s_c1[w][e] = c1[e]; }
    }
    __syncthreads();
    if (tid < NE) {
        float gs = 0.f; int a = 0, b = 0;
        for (int w2 = 0; w2 < 8; w2++) { gs += s_gs[w2][tid]; a += s_c0[w2][tid]; b += s_c1[w2][tid]; }
        g_gs[blockIdx.x][tid] = gs;
        g_cnt[blockIdx.x][tid][0] = a;
        g_cnt[blockIdx.x][tid][1] = b;
    }
}

// ---------------- K2: block scan + totals + loss ----------------
__global__ __launch_bounds__(256) void k2_scan(float* __restrict__ loss_out) {
    __shared__ int   s_cnt[NB1][16];
    __shared__ float s_g[NB1][NE];
    __shared__ int   s_tot[16];
    __shared__ float s_red[32][NE];
    int tid = threadIdx.x;
    for (int i = tid; i < NB1 * 16; i += 256) s_cnt[i >> 4][i & 15] = ((const int*)g_cnt)[i];
    for (int i = tid; i < NB1 * NE; i += 256) s_g[i >> 3][i & 7] = ((const float*)g_gs)[i];
    __syncthreads();
    if (tid < 16) {
        int run = 0;
        for (int b = 0; b < NB1; b++) { int v = s_cnt[b][tid]; s_cnt[b][tid] = run; run += v; }
        s_tot[tid] = run;
    }
    {
        int e = tid & 7, grp = tid >> 3;
        float p = 0.f;
        for (int b = grp * 8; b < grp * 8 + 8; b++) p += s_g[b][e];
        s_red[grp][e] = p;
    }
    __syncthreads();
    for (int i = tid; i < NB1 * 16; i += 256) ((int*)g_blkoff)[i] = s_cnt[i >> 4][i & 15];
    if (tid == 0) {
        int base = 0;
        for (int e = 0; e < NE; e++) {
            int c0t = s_tot[e * 2 + 0], c1t = s_tot[e * 2 + 1];
            g_cnt0[e] = c0t;
            int v0 = c0t < CAPX ? c0t : CAPX;
            int lim1 = CAPX - c0t; if (lim1 < 0) lim1 = 0;
            int v1 = c1t < lim1 ? c1t : lim1;
            g_valid0[e] = v0; g_lim1[e] = lim1;
            g_base[e] = base; g_vcnt[e] = v0 + v1;
            base += v0 + v1;
        }
        float loss = 0.f;
        for (int e = 0; e < NE; e++) {
            float gs = 0.f;
            for (int grp = 0; grp < 32; grp++) gs += s_red[grp][e];
            float me = gs / (float)TS;
            float ce = (float)s_tot[e * 2] / (float)TS;
            loss += me * ce;
        }
        *loss_out = loss * (float)NE;
    }
}

// ---------------- K3: deterministic ranks -> compacted assignment lists ----------------
__global__ __launch_bounds__(256) void k3_build() {
    __shared__ int wcnt[8][NE][2];
    __shared__ int wpre[8][NE][2];
    int tid = threadIdx.x, w = tid >> 5, lane = tid & 31;
    int t = blockIdx.x * 256 + tid;   // warp w covers consecutive tokens, lane ascending
    int e0 = g_e0[t], e1 = g_e1[t];
    float g0 = g_g0[t], g1 = g_g1[t];
    if (tid < 128) ((int*)wcnt)[tid] = 0;
    __syncthreads();
    unsigned m0 = __match_any_sync(0xffffffffu, e0);
    unsigned m1 = __match_any_sync(0xffffffffu, e1);
    unsigned lt = (1u << lane) - 1u;
    int r0 = __popc(m0 & lt);
    int r1 = __popc(m1 & lt);
    if ((m0 & lt) == 0) wcnt[w][e0][0] = __popc(m0);
    if ((m1 & lt) == 0) wcnt[w][e1][1] = __popc(m1);
    __syncthreads();
    if (tid < 16) {
        int e = tid >> 1, k = tid & 1;
        int run = 0;
        for (int w2 = 0; w2 < 8; w2++) { wpre[w2][e][k] = run; run += wcnt[w2][e][k]; }
    }
    __syncthreads();
    int b = blockIdx.x;
    int R0 = g_blkoff[b][e0][0] + wpre[w][e0][0] + r0;
    int R1 = g_blkoff[b][e1][1] + wpre[w][e1][1] + r1;
    if (R0 < CAPX) { int p = g_base[e0] + R0; g_atok[p] = t; g_agate[p] = g0; }
    if (R1 < g_lim1[e1]) { int p = g_base[e1] + g_valid0[e1] + R1; g_atok[p] = t; g_agate[p] = g1; }
}

// ---------------- K4: fused expert FFN (fp32 tiled GEMM x2) ----------------
__global__ __launch_bounds__(256, 2) void k4_ffn(
    const float* __restrict__ x,
    const float* __restrict__ w1, const float* __restrict__ b1,
    const float* __restrict__ w2, const float* __restrict__ b2,
    float* __restrict__ y) {
    int e = blockIdx.y;
    int cnt = g_vcnt[e];
    int row0 = blockIdx.x * 64;
    if (row0 >= cnt) return;
    int rows = min(64, cnt - row0);
    int base = g_base[e] + row0;

    extern __shared__ float sm[];
    float* XsT = sm;                      // [256][PITCH]
    float* HsT = XsT + 256 * PITCH;       // [64][PITCH]
    float* W1s = HsT + 64 * PITCH;        // [32][64]
    float* W2s = W1s + 32 * 64;           // [16][256]
    int*   toks = (int*)(W2s + 16 * 256); // [64]
    float* gts  = (float*)(toks + 64);    // [64]

    int tid = threadIdx.x;
    if (tid < 64) {
        if (tid < rows) { toks[tid] = g_atok[base + tid]; gts[tid] = g_agate[base + tid]; }
        else            { toks[tid] = 0; gts[tid] = 0.f; }
    }
    __syncthreads();
    {   // gather X tile transposed into smem
        int i = tid >> 2, part = tid & 3;
        const float4* xr = (const float4*)(x + (size_t)toks[i] * MD);
        bool live = i < rows;
#pragma unroll
        for (int j = 0; j < 16; j++) {
            int c4 = part * 16 + j;
            float4 v = live ? xr[c4] : make_float4(0.f, 0.f, 0.f, 0.f);
            int c = c4 * 4;
            XsT[(c + 0) * PITCH + i] = v.x;
            XsT[(c + 1) * PITCH + i] = v.y;
            XsT[(c + 2) * PITCH + i] = v.z;
            XsT[(c + 3) * PITCH + i] = v.w;
        }
    }
    int tg = tid >> 4;   // GEMM1: h-group   | GEMM2: token-group
    int mg = tid & 15;   // GEMM1: tok-group | GEMM2: m-group

    float acc[4][16];
#pragma unroll
    for (int b = 0; b < 4; b++)
#pragma unroll
        for (int j = 0; j < 16; j++) acc[b][j] = 0.f;

    for (int hc = 0; hc < 16; hc++) {
        float hacc[4][4];
#pragma unroll
        for (int a = 0; a < 4; a++)
#pragma unroll
            for (int b = 0; b < 4; b++) hacc[a][b] = 0.f;

        // ---- GEMM1: H_c(64x64) = X(64x256) @ W1[:, hc*64..] ----
        for (int ks = 0; ks < MD; ks += 32) {
            __syncthreads();
#pragma unroll
            for (int rep = 0; rep < 2; rep++) {
                int f = tid + rep * 256;             // [32][16] float4s
                int r = f >> 4, c4 = f & 15;
                float4 v = *(const float4*)(w1 + ((size_t)(e * MD + ks + r) * NH + hc * 64 + c4 * 4));
                *(float4*)&W1s[r * 64 + c4 * 4] = v;
            }
            __syncthreads();
#pragma unroll
            for (int s = 0; s < 32; s++) {
                float4 xv = *(const float4*)&XsT[(ks + s) * PITCH + mg * 4];
                float4 wv = *(const float4*)&W1s[s * 64 + tg * 4];
                hacc[0][0] += wv.x * xv.x; hacc[0][1] += wv.x * xv.y; hacc[0][2] += wv.x * xv.z; hacc[0][3] += wv.x * xv.w;
                hacc[1][0] += wv.y * xv.x; hacc[1][1] += wv.y * xv.y; hacc[1][2] += wv.y * xv.z; hacc[1][3] += wv.y * xv.w;
                hacc[2][0] += wv.z * xv.x; hacc[2][1] += wv.z * xv.y; hacc[2][2] += wv.z * xv.z; hacc[2][3] += wv.z * xv.w;
                hacc[3][0] += wv.w * xv.x; hacc[3][1] += wv.w * xv.y; hacc[3][2] += wv.w * xv.z; hacc[3][3] += wv.w * xv.w;
            }
        }
        {   // bias + relu, store H transposed
            const float* b1p = b1 + e * NH + hc * 64;
#pragma unroll
            for (int a = 0; a < 4; a++) {
                int h = tg * 4 + a;
                float bv = b1p[h];
                float4 o;
                o.x = fmaxf(hacc[a][0] + bv, 0.f);
                o.y = fmaxf(hacc[a][1] + bv, 0.f);
                o.z = fmaxf(hacc[a][2] + bv, 0.f);
                o.w = fmaxf(hacc[a][3] + bv, 0.f);
                *(float4*)&HsT[h * PITCH + mg * 4] = o;
            }
        }
        // ---- GEMM2: Out(64x256) += H_c(64x64) @ W2[hc*64.., :] ----
        for (int ks = 0; ks < 64; ks += 16) {
            __syncthreads();
#pragma unroll
            for (int q = 0; q < 4; q++) {
                int f = tid + q * 256;               // [16][64] float4s
                int r = f >> 6, c4 = f & 63;
                float4 v = *(const float4*)(w2 + ((size_t)(e * NH + hc * 64 + ks + r) * MD + c4 * 4));
                *(float4*)&W2s[r * 256 + c4 * 4] = v;
            }
            __syncthreads();
#pragma unroll
            for (int s = 0; s < 16; s++) {
                float4 hv = *(const float4*)&HsT[(ks + s) * PITCH + tg * 4];
                const float* wrow = &W2s[s * 256 + mg];   // stride-16 scalar: conflict-free
#pragma unroll
                for (int j = 0; j < 16; j++) {
                    float wvv = wrow[j * 16];
                    acc[0][j] += hv.x * wvv;
                    acc[1][j] += hv.y * wvv;
                    acc[2][j] += hv.z * wvv;
                    acc[3][j] += hv.w * wvv;
                }
            }
        }
    }
    // ---- epilogue: y[token] += gate * (out + b2) (<=2 adds per element: deterministic) ----
    const float* b2p = b2 + e * MD;
#pragma unroll
    for (int b = 0; b < 4; b++) {
        int t = tg * 4 + b;
        if (t < rows) {
            float g = gts[t];
            float* yr = y + (size_t)toks[t] * MD;
#pragma unroll
            for (int j = 0; j < 16; j++) {
                int m = mg + 16 * j;
                atomicAdd(&yr[m], g * (acc[b][j] + b2p[m]));
            }
        }
    }
}

// ---------------- launcher ----------------
extern "C" void kernel_launch(void* const* d_in, const int* in_sizes, int n_in,
                              void* d_out, int out_size) {
    const float* x  = (const float*)d_in[0];
    const float* wg = (const float*)d_in[1];
    const float* w1 = (const float*)d_in[2];
    const float* b1 = (const float*)d_in[3];
    const float* w2 = (const float*)d_in[4];
    const float* b2 = (const float*)d_in[5];
    float* y = (float*)d_out;
    float* loss = y + (size_t)TS * MD;

    cudaMemsetAsync(y, 0, (size_t)TS * MD * sizeof(float));
    k1_gate<<<NB1, 256>>>(x, wg);
    k2_scan<<<1, 256>>>(loss);
    k3_build<<<NB1, 256>>>();

    int smem = (256 * PITCH + 64 * PITCH + 32 * 64 + 16 * 256 + 128) * 4;  // 112128 B
    cudaFuncSetAttribute(k4_ffn, cudaFuncAttributeMaxDynamicSharedMemorySize, smem);
    k4_ffn<<<dim3((CAPX + 63) / 64, NE), 256, smem>>>(x, w1, b1, w2, b2, y);
}